// round 8
// baseline (speedup 1.0000x reference)
#include <cuda_runtime.h>
#include <math.h>

// Problem constants
#define BB 64
#define SS 1024
#define HH 128
#define AA 8
#define WIN 5
#define PADW 2
#define STILE 128            // s-tile for logits kernel
#define GROWS (STILE + 4)    // 132 padded rows in logits tile
#define CCH 64               // s per ctx block
#define NCH (SS / CCH)       // 16 coarse ctx chunks
#define RPW 1028             // ctx rbuf pitch (floats): 16B-aligned, bank-scattered

// Scratch (no allocations allowed)
// Packed G: [h][w][8] with inner order (a0,a4,a1,a5,a2,a6,a3,a7) so a 16B load
// yields two 64-bit (G[a],G[a+4]) pairs for fma.rn.f32x2.
__device__ float4 gGp4[HH * WIN * 2];                // 128*5*8 floats
__device__ float gLogits[AA * BB * SS];              // [a][b][s]
__device__ float gCtxPart[NCH * AA * BB * HH];       // [sc][a][b][h]  (4.2MB)

__device__ __forceinline__ void fma2(unsigned long long& acc,
                                     unsigned long long d2,
                                     unsigned long long g2) {
    asm("fma.rn.f32x2 %0, %1, %2, %3;" : "=l"(acc) : "l"(d2), "l"(g2), "l"(acc));
}
__device__ __forceinline__ unsigned long long dup2(float v) {
    unsigned long long r;
    asm("mov.b64 %0, {%1, %1};" : "=l"(r) : "f"(v));
    return r;
}
__device__ __forceinline__ unsigned long long pk2(float lo, float hi) {
    unsigned long long r;
    asm("mov.b64 %0, {%1, %2};" : "=l"(r) : "f"(lo), "f"(hi));
    return r;
}
__device__ __forceinline__ void unpk(unsigned long long p, float& lo, float& hi) {
    asm("mov.b64 {%0, %1}, %2;" : "=f"(lo), "=f"(hi) : "l"(p));
}

// ---------------------------------------------------------------------------
// K1: G[a,h,w] = sum_f P[a,h,f] * E[a,f,w]; packed scatter to gGp4.
// grid = (A, 4), block = 128. thread: h = hg*32 + (t>>2), f-quarter q = t&3.
// ---------------------------------------------------------------------------
__global__ void k_prep(const float* __restrict__ P, const float* __restrict__ E) {
    __shared__ float Esm[HH * WIN];
    int a = blockIdx.x, hg = blockIdx.y, t = threadIdx.x;
    int h = hg * 32 + (t >> 2), q = t & 3;

    for (int i = t; i < HH * WIN; i += 128)
        Esm[i] = E[(size_t)a * HH * WIN + i];
    __syncthreads();

    const float4* Pp = (const float4*)(P + (size_t)a * HH * HH + h * HH + q * 32);
    float g[WIN] = {0.f, 0.f, 0.f, 0.f, 0.f};
    #pragma unroll
    for (int i = 0; i < 8; ++i) {
        float4 p = Pp[i];
        int f0 = q * 32 + i * 4;
        #pragma unroll
        for (int w = 0; w < WIN; ++w) {
            g[w] += p.x * Esm[(f0 + 0) * WIN + w];
            g[w] += p.y * Esm[(f0 + 1) * WIN + w];
            g[w] += p.z * Esm[(f0 + 2) * WIN + w];
            g[w] += p.w * Esm[(f0 + 3) * WIN + w];
        }
    }
    #pragma unroll
    for (int w = 0; w < WIN; ++w) {
        g[w] += __shfl_xor_sync(0xffffffffu, g[w], 1);
        g[w] += __shfl_xor_sync(0xffffffffu, g[w], 2);
    }
    if (q == 0) {
        float* Gp = (float*)gGp4;
        #pragma unroll
        for (int w = 0; w < WIN; ++w)
            Gp[(h * WIN + w) * 8 + (a & 3) * 2 + (a >> 2)] = g[w];
    }
}

// ---------------------------------------------------------------------------
// K2: logits[a,b,s] = sum_w sum_h doc[b, s+w-2, h] * G[a,h,w]
// R5-proven inner mix (lane -> 4 consecutive s), but 256 threads/block with
// warp -> 16-h split: doubles warps/SM at identical smem (88KB, 2 blocks/SM).
// dsm pitch 128, XOR swizzle col = h ^ ((row>>2)&31).
// grid = (S/128, B), block = 256.
// ---------------------------------------------------------------------------
__global__ void __launch_bounds__(256) k_logits(const float* __restrict__ doc) {
    extern __shared__ float sm[];
    float* dsm = sm;                         // [GROWS][128] swizzled
    float* Gsm = sm + GROWS * HH;            // [H*WIN*8] packed pairs
    int b  = blockIdx.y;
    int s0 = blockIdx.x * STILE;
    int t  = threadIdx.x;
    int wid = t >> 5, lane = t & 31;

    {
        const float4* src = gGp4;
        float4* dst = (float4*)Gsm;
        #pragma unroll
        for (int i = t; i < HH * WIN * 2; i += 256) dst[i] = src[i];
    }

    const float* db = doc + (size_t)b * SS * HH;
    for (int row = wid; row < GROWS; row += 8) {
        int gs = s0 - PADW + row;
        int swz = (row >> 2) & 31;
        const float* src = db + (size_t)gs * HH;
        #pragma unroll
        for (int m = 0; m < 4; ++m) {
            int c = lane + 32 * m;
            float v = (gs >= 0 && gs < SS) ? src[c] : 0.f;
            dsm[row * HH + (c ^ swz)] = v;
        }
    }
    __syncthreads();

    int h0 = wid * 16;
    int st0 = 4 * lane;
    unsigned long long acc[4][4];
    #pragma unroll
    for (int i = 0; i < 4; ++i)
        #pragma unroll
        for (int p = 0; p < 4; ++p) acc[i][p] = 0ull;

    #pragma unroll 2
    for (int hh = 0; hh < 16; ++hh) {
        int h = h0 + hh;
        unsigned long long d[8];
        #pragma unroll
        for (int r = 0; r < 8; ++r) {
            int row = st0 + r;
            d[r] = dup2(dsm[row * HH + (h ^ ((row >> 2) & 31))]);
        }
        const float* gh = &Gsm[h * (WIN * 8)];
        #pragma unroll
        for (int w = 0; w < WIN; ++w) {
            ulonglong2 g01 = *(const ulonglong2*)(gh + w * 8);
            ulonglong2 g23 = *(const ulonglong2*)(gh + w * 8 + 4);
            #pragma unroll
            for (int si = 0; si < 4; ++si) {
                fma2(acc[si][0], d[si + w], g01.x);
                fma2(acc[si][1], d[si + w], g01.y);
                fma2(acc[si][2], d[si + w], g23.x);
                fma2(acc[si][3], d[si + w], g23.y);
            }
        }
    }

    // Cross-warp h-reduction: red[st][65], slot = a*8 + wid (8 warp-partials).
    __syncthreads();
    float* red = sm;   // 128*65 floats = 33.3KB, fits in dsm region
    #pragma unroll
    for (int si = 0; si < 4; ++si) {
        int st = st0 + si;
        #pragma unroll
        for (int p = 0; p < 4; ++p) {
            float lo, hi;
            unpk(acc[si][p], lo, hi);
            red[st * 65 + p * 8 + wid] = lo;           // aspect p
            red[st * 65 + (p + 4) * 8 + wid] = hi;     // aspect p+4
        }
    }
    __syncthreads();

    int st = t & 127, half = t >> 7;
    #pragma unroll
    for (int j = 0; j < 4; ++j) {
        int a = half * 4 + j;
        const float* rp = &red[st * 65 + a * 8];
        float v = ((rp[0] + rp[1]) + (rp[2] + rp[3])) +
                  ((rp[4] + rp[5]) + (rp[6] + rp[7]));
        gLogits[((size_t)a * BB + b) * SS + s0 + st] = v;
    }
}

// ---------------------------------------------------------------------------
// K3: attn = softmax_s(logits); write to out[b][a][s]
// grid = A*B (row = a*B + b), block = 256
// ---------------------------------------------------------------------------
__global__ void k_softmax(float* __restrict__ out) {
    int row = blockIdx.x;
    int a = row >> 6;
    int b = row & 63;
    const float* lg = gLogits + (size_t)row * SS;
    int t = threadIdx.x;

    float v[4];
    float m = -3.4e38f;
    #pragma unroll
    for (int i = 0; i < 4; ++i) { v[i] = lg[t + i * 256]; m = fmaxf(m, v[i]); }

    __shared__ float redm[8];
    #pragma unroll
    for (int o = 16; o > 0; o >>= 1) m = fmaxf(m, __shfl_xor_sync(0xffffffffu, m, o));
    if ((t & 31) == 0) redm[t >> 5] = m;
    __syncthreads();
    m = redm[0];
    #pragma unroll
    for (int i = 1; i < 8; ++i) m = fmaxf(m, redm[i]);

    float sl = 0.f;
    #pragma unroll
    for (int i = 0; i < 4; ++i) { v[i] = __expf(v[i] - m); sl += v[i]; }
    __shared__ float reds[8];
    #pragma unroll
    for (int o = 16; o > 0; o >>= 1) sl += __shfl_xor_sync(0xffffffffu, sl, o);
    if ((t & 31) == 0) reds[t >> 5] = sl;
    __syncthreads();
    float tot = 0.f;
    #pragma unroll
    for (int i = 0; i < 8; ++i) tot += reds[i];
    float inv = 1.0f / tot;

    float* op = out + ((size_t)b * AA + a) * SS;
    #pragma unroll
    for (int i = 0; i < 4; ++i) op[t + i * 256] = v[i] * inv;
}

// ---------------------------------------------------------------------------
// K4: ctx partials. grid = (B, 16), block = 128 (4 warps), CCH=64.
// Warp w owns s in [w*16, w*16+16); lane = h-quad, so each warp LDG.128
// covers one full 512B doc row. 4-warp smem reduce, coalesced store.
// ---------------------------------------------------------------------------
__global__ void __launch_bounds__(128) k_ctx(const float* __restrict__ doc,
                                             const float* __restrict__ attn) {
    int b = blockIdx.x, sc = blockIdx.y;
    int t = threadIdx.x, w = t >> 5, lane = t & 31;

    __shared__ float asmem[AA * CCH];     // 2KB
    __shared__ float rbuf[4 * RPW];       // 16.4KB
    #pragma unroll
    for (int i = t; i < AA * CCH; i += 128) {
        int a = i >> 6, s = i & 63;
        asmem[i] = attn[((size_t)b * AA + a) * SS + sc * CCH + s];
    }
    __syncthreads();

    const float4* dp = (const float4*)(doc + ((size_t)b * SS + sc * CCH) * HH) + lane;
    unsigned long long acc[AA][2];
    #pragma unroll
    for (int a = 0; a < AA; ++a) { acc[a][0] = 0ull; acc[a][1] = 0ull; }

    int sb = w * 16;
    #pragma unroll 8
    for (int i = 0; i < 16; ++i) {
        int s = sb + i;
        float4 dv = dp[s * 32];                    // coalesced 512B/warp LDG.128
        unsigned long long dxy = pk2(dv.x, dv.y);
        unsigned long long dzw = pk2(dv.z, dv.w);
        #pragma unroll
        for (int a = 0; a < AA; ++a) {
            unsigned long long av = dup2(asmem[a * CCH + s]);   // broadcast
            fma2(acc[a][0], dxy, av);
            fma2(acc[a][1], dzw, av);
        }
    }

    #pragma unroll
    for (int a = 0; a < AA; ++a) {
        float4 o;
        unpk(acc[a][0], o.x, o.y);
        unpk(acc[a][1], o.z, o.w);
        *(float4*)&rbuf[w * RPW + a * HH + lane * 4] = o;   // conflict-free STS.128
    }
    __syncthreads();

    // Reduce over the 4 warps: thread t -> h = t; k -> aspect.
    #pragma unroll
    for (int k = 0; k < AA; ++k) {
        int slot = k * HH + t;
        float v = (rbuf[slot] + rbuf[RPW + slot]) +
                  (rbuf[2 * RPW + slot] + rbuf[3 * RPW + slot]);
        gCtxPart[(((size_t)sc * AA + k) * BB + b) * HH + t] = v;   // coalesced
    }
}

// ---------------------------------------------------------------------------
// K5: rep[b,a,f] = sum_h ctx[a,b,h] * P[a,h,f], ctx reduced over 16 partials
// grid = B*A (blk = b*A + a), block = 128 (thread = f)
// ---------------------------------------------------------------------------
__global__ void k_rep(const float* __restrict__ P, float* __restrict__ out) {
    int blk = blockIdx.x;
    int a = blk & 7, b = blk >> 3;
    int f = threadIdx.x;
    __shared__ float csm[HH];
    float c = 0.f;
    #pragma unroll
    for (int sc = 0; sc < NCH; ++sc)
        c += gCtxPart[(((size_t)sc * AA + a) * BB + b) * HH + f];
    csm[f] = c;
    __syncthreads();

    float acc = 0.f;
    const float* Pp = P + (size_t)a * HH * HH + f;
    #pragma unroll 8
    for (int h = 0; h < HH; ++h) acc += csm[h] * Pp[(size_t)h * HH];

    out[(size_t)BB * AA * SS + ((size_t)b * AA + a) * HH + f] = acc;
}

// ---------------------------------------------------------------------------
extern "C" void kernel_launch(void* const* d_in, const int* in_sizes, int n_in,
                              void* d_out, int out_size) {
    const float* doc = (const float*)d_in[0];   // (B,S,H)
    const float* E   = (const float*)d_in[1];   // (A, WIN*H)
    const float* P   = (const float*)d_in[2];   // (A,H,H)
    float* out = (float*)d_out;                 // [attn (B,A,S) | rep (B,A,H)]

    size_t sm2 = (size_t)(GROWS * HH + HH * WIN * 8) * sizeof(float);  // ~88.1 KB
    cudaFuncSetAttribute(k_logits, cudaFuncAttributeMaxDynamicSharedMemorySize, (int)sm2);

    k_prep<<<dim3(AA, 4), 128>>>(P, E);
    k_logits<<<dim3(SS / STILE, BB), 256, sm2>>>(doc);
    k_softmax<<<AA * BB, 256>>>(out);
    k_ctx<<<dim3(BB, NCH), 128>>>(doc, out);
    k_rep<<<BB * AA, 128>>>(P, out);
}

// round 9
// speedup vs baseline: 1.0394x; 1.0394x over previous
#include <cuda_runtime.h>
#include <math.h>

// Problem constants
#define BB 64
#define SS 1024
#define HH 128
#define AA 8
#define WIN 5
#define PADW 2
#define STILE 128            // s-tile for logits kernel
#define GROWS (STILE + 4)    // 132 padded rows in logits tile
#define CCH 64               // s per ctx block
#define NCH (SS / CCH)       // 16 coarse ctx chunks
#define RP4 257              // ctx rbuf pitch in float4 (pad 1)

// Scratch (no allocations allowed)
// Packed G: [h][w][8] with inner order (a0,a4,a1,a5,a2,a6,a3,a7) so a 16B load
// yields two 64-bit (G[a],G[a+4]) pairs for fma.rn.f32x2.
__device__ float4 gGp4[HH * WIN * 2];                // 128*5*8 floats
__device__ float gLogits[AA * BB * SS];              // [a][b][s]
__device__ float gCtxPart[NCH * AA * BB * HH];       // [sc][a][b][h]  (4.2MB)

__device__ __forceinline__ void fma2(unsigned long long& acc,
                                     unsigned long long d2,
                                     unsigned long long g2) {
    asm("fma.rn.f32x2 %0, %1, %2, %3;" : "=l"(acc) : "l"(d2), "l"(g2), "l"(acc));
}
__device__ __forceinline__ unsigned long long dup2(float v) {
    unsigned long long r;
    asm("mov.b64 %0, {%1, %1};" : "=l"(r) : "f"(v));
    return r;
}
__device__ __forceinline__ unsigned long long pk2(float lo, float hi) {
    unsigned long long r;
    asm("mov.b64 %0, {%1, %2};" : "=l"(r) : "f"(lo), "f"(hi));
    return r;
}
__device__ __forceinline__ void unpk(unsigned long long p, float& lo, float& hi) {
    asm("mov.b64 {%0, %1}, %2;" : "=f"(lo), "=f"(hi) : "l"(p));
}

// ---------------------------------------------------------------------------
// K1: G[a,h,w] = sum_f P[a,h,f] * E[a,f,w]; packed scatter to gGp4.
// grid = (A, 4), block = 128. thread: h = hg*32 + (t>>2), f-quarter q = t&3.
// ---------------------------------------------------------------------------
__global__ void k_prep(const float* __restrict__ P, const float* __restrict__ E) {
    __shared__ float Esm[HH * WIN];
    int a = blockIdx.x, hg = blockIdx.y, t = threadIdx.x;
    int h = hg * 32 + (t >> 2), q = t & 3;

    for (int i = t; i < HH * WIN; i += 128)
        Esm[i] = E[(size_t)a * HH * WIN + i];
    __syncthreads();

    const float4* Pp = (const float4*)(P + (size_t)a * HH * HH + h * HH + q * 32);
    float g[WIN] = {0.f, 0.f, 0.f, 0.f, 0.f};
    #pragma unroll
    for (int i = 0; i < 8; ++i) {
        float4 p = Pp[i];
        int f0 = q * 32 + i * 4;
        #pragma unroll
        for (int w = 0; w < WIN; ++w) {
            g[w] += p.x * Esm[(f0 + 0) * WIN + w];
            g[w] += p.y * Esm[(f0 + 1) * WIN + w];
            g[w] += p.z * Esm[(f0 + 2) * WIN + w];
            g[w] += p.w * Esm[(f0 + 3) * WIN + w];
        }
    }
    #pragma unroll
    for (int w = 0; w < WIN; ++w) {
        g[w] += __shfl_xor_sync(0xffffffffu, g[w], 1);
        g[w] += __shfl_xor_sync(0xffffffffu, g[w], 2);
    }
    if (q == 0) {
        float* Gp = (float*)gGp4;
        #pragma unroll
        for (int w = 0; w < WIN; ++w)
            Gp[(h * WIN + w) * 8 + (a & 3) * 2 + (a >> 2)] = g[w];
    }
}

// ---------------------------------------------------------------------------
// K2: logits[a,b,s] = sum_w sum_h doc[b, s+w-2, h] * G[a,h,w]
// (R7-proven version, untouched) lane -> 4 consecutive s, warp -> 32-h split.
// dsm pitch 128, XOR swizzle col = h ^ ((row>>2)&31).
// grid = (S/128, B), block = 128, smem 88KB.
// ---------------------------------------------------------------------------
__global__ void __launch_bounds__(128) k_logits(const float* __restrict__ doc) {
    extern __shared__ float sm[];
    float* dsm = sm;                         // [GROWS][128] swizzled
    float* Gsm = sm + GROWS * HH;            // [H*WIN*8] packed pairs
    int b  = blockIdx.y;
    int s0 = blockIdx.x * STILE;
    int t  = threadIdx.x;
    int wid = t >> 5, lane = t & 31;

    {
        const float4* src = gGp4;
        float4* dst = (float4*)Gsm;
        #pragma unroll
        for (int i = t; i < HH * WIN * 2; i += HH) dst[i] = src[i];
    }

    const float* db = doc + (size_t)b * SS * HH;
    for (int row = wid; row < GROWS; row += 4) {
        int gs = s0 - PADW + row;
        int swz = (row >> 2) & 31;
        const float* src = db + (size_t)gs * HH;
        #pragma unroll
        for (int m = 0; m < 4; ++m) {
            int c = lane + 32 * m;
            float v = (gs >= 0 && gs < SS) ? src[c] : 0.f;
            dsm[row * HH + (c ^ swz)] = v;
        }
    }
    __syncthreads();

    int h0 = wid * 32;
    int st0 = 4 * lane;
    unsigned long long acc[4][4];
    #pragma unroll
    for (int i = 0; i < 4; ++i)
        #pragma unroll
        for (int p = 0; p < 4; ++p) acc[i][p] = 0ull;

    #pragma unroll 2
    for (int hh = 0; hh < 32; ++hh) {
        int h = h0 + hh;
        unsigned long long d[8];
        #pragma unroll
        for (int r = 0; r < 8; ++r) {
            int row = st0 + r;
            d[r] = dup2(dsm[row * HH + (h ^ ((row >> 2) & 31))]);
        }
        const float* gh = &Gsm[h * (WIN * 8)];
        #pragma unroll
        for (int w = 0; w < WIN; ++w) {
            ulonglong2 g01 = *(const ulonglong2*)(gh + w * 8);
            ulonglong2 g23 = *(const ulonglong2*)(gh + w * 8 + 4);
            #pragma unroll
            for (int si = 0; si < 4; ++si) {
                fma2(acc[si][0], d[si + w], g01.x);
                fma2(acc[si][1], d[si + w], g01.y);
                fma2(acc[si][2], d[si + w], g23.x);
                fma2(acc[si][3], d[si + w], g23.y);
            }
        }
    }

    __syncthreads();
    float* red = sm;   // 128*33 floats, fits in dsm region
    #pragma unroll
    for (int si = 0; si < 4; ++si) {
        int st = st0 + si;
        #pragma unroll
        for (int p = 0; p < 4; ++p) {
            float lo, hi;
            unpk(acc[si][p], lo, hi);
            red[st * 33 + p * 4 + wid] = lo;           // aspect p
            red[st * 33 + (p + 4) * 4 + wid] = hi;     // aspect p+4
        }
    }
    __syncthreads();

    int st = t;
    #pragma unroll
    for (int a = 0; a < AA; ++a) {
        const float* rp = &red[st * 33 + a * 4];
        float v = rp[0] + rp[1] + rp[2] + rp[3];
        gLogits[((size_t)a * BB + b) * SS + s0 + st] = v;
    }
}

// ---------------------------------------------------------------------------
// K3: attn = softmax_s(logits); write to out[b][a][s]
// grid = A*B (row = a*B + b), block = 256
// ---------------------------------------------------------------------------
__global__ void k_softmax(float* __restrict__ out) {
    int row = blockIdx.x;
    int a = row >> 6;
    int b = row & 63;
    const float* lg = gLogits + (size_t)row * SS;
    int t = threadIdx.x;

    float v[4];
    float m = -3.4e38f;
    #pragma unroll
    for (int i = 0; i < 4; ++i) { v[i] = lg[t + i * 256]; m = fmaxf(m, v[i]); }

    __shared__ float redm[8];
    #pragma unroll
    for (int o = 16; o > 0; o >>= 1) m = fmaxf(m, __shfl_xor_sync(0xffffffffu, m, o));
    if ((t & 31) == 0) redm[t >> 5] = m;
    __syncthreads();
    m = redm[0];
    #pragma unroll
    for (int i = 1; i < 8; ++i) m = fmaxf(m, redm[i]);

    float sl = 0.f;
    #pragma unroll
    for (int i = 0; i < 4; ++i) { v[i] = __expf(v[i] - m); sl += v[i]; }
    __shared__ float reds[8];
    #pragma unroll
    for (int o = 16; o > 0; o >>= 1) sl += __shfl_xor_sync(0xffffffffu, sl, o);
    if ((t & 31) == 0) reds[t >> 5] = sl;
    __syncthreads();
    float tot = 0.f;
    #pragma unroll
    for (int i = 0; i < 8; ++i) tot += reds[i];
    float inv = 1.0f / tot;

    float* op = out + ((size_t)b * AA + a) * SS;
    #pragma unroll
    for (int i = 0; i < 4; ++i) op[t + i * 256] = v[i] * inv;
}

// ---------------------------------------------------------------------------
// K4 v4: ctx partials, low-reg / high-occ. grid = (B, 16), block = 256.
// Thread = (h-pair hp = t&63, s-group sg = t>>6). Each 64-thread group reads
// full 512B doc rows via float2 (coalesced), 8 f32x2 accumulators (16 regs).
// 4-group smem reduce through padded float4 rbuf, coalesced float4 store.
// ---------------------------------------------------------------------------
__global__ void __launch_bounds__(256) k_ctx(const float* __restrict__ doc,
                                             const float* __restrict__ attn) {
    int b = blockIdx.x, sc = blockIdx.y;
    int t = threadIdx.x;
    int hp = t & 63, sg = t >> 6;

    __shared__ float asmem[AA * CCH];       // 2KB
    __shared__ float4 rbuf4[4 * RP4];       // 16.4KB
    #pragma unroll
    for (int i = t; i < AA * CCH; i += 256) {
        int a = i >> 6, s = i & 63;
        asmem[i] = attn[((size_t)b * AA + a) * SS + sc * CCH + s];
    }
    __syncthreads();

    const float2* dp = (const float2*)(doc + ((size_t)b * SS + sc * CCH) * HH) + hp;
    unsigned long long acc[AA];
    #pragma unroll
    for (int a = 0; a < AA; ++a) acc[a] = 0ull;

    int sb = sg * 16;
    #pragma unroll 8
    for (int i = 0; i < 16; ++i) {
        int s = sb + i;
        float2 dv = dp[s * 64];                    // coalesced LDG.64 (512B/group)
        unsigned long long dxy = pk2(dv.x, dv.y);
        #pragma unroll
        for (int a = 0; a < AA; ++a) {
            unsigned long long av = dup2(asmem[a * CCH + s]);   // broadcast
            fma2(acc[a], dxy, av);
        }
    }

    // Store partials: per sg region (pitch RP4 float4 = 1028 floats).
    {
        float* rb = (float*)&rbuf4[sg * RP4];
        #pragma unroll
        for (int a = 0; a < AA; ++a) {
            float lo, hi;
            unpk(acc[a], lo, hi);
            *(float2*)&rb[a * HH + 2 * hp] = make_float2(lo, hi);  // STS.64 c-free
        }
    }
    __syncthreads();

    // Reduce over the 4 s-groups: thread t -> float4 slot t (a = t>>5).
    float4 v0 = rbuf4[t], v1 = rbuf4[RP4 + t];
    float4 v2 = rbuf4[2 * RP4 + t], v3 = rbuf4[3 * RP4 + t];
    float4 o;
    o.x = (v0.x + v1.x) + (v2.x + v3.x);
    o.y = (v0.y + v1.y) + (v2.y + v3.y);
    o.z = (v0.z + v1.z) + (v2.z + v3.z);
    o.w = (v0.w + v1.w) + (v2.w + v3.w);
    int a = t >> 5, h4 = t & 31;
    *((float4*)(gCtxPart + (((size_t)sc * AA + a) * BB + b) * HH) + h4) = o;
}

// ---------------------------------------------------------------------------
// K5: rep[b,a,f] = sum_h ctx[a,b,h] * P[a,h,f], ctx reduced over 16 partials
// grid = B*A (blk = b*A + a), block = 128 (thread = f)
// ---------------------------------------------------------------------------
__global__ void k_rep(const float* __restrict__ P, float* __restrict__ out) {
    int blk = blockIdx.x;
    int a = blk & 7, b = blk >> 3;
    int f = threadIdx.x;
    __shared__ float csm[HH];
    float c = 0.f;
    #pragma unroll
    for (int sc = 0; sc < NCH; ++sc)
        c += gCtxPart[(((size_t)sc * AA + a) * BB + b) * HH + f];
    csm[f] = c;
    __syncthreads();

    float acc = 0.f;
    const float* Pp = P + (size_t)a * HH * HH + f;
    #pragma unroll 8
    for (int h = 0; h < HH; ++h) acc += csm[h] * Pp[(size_t)h * HH];

    out[(size_t)BB * AA * SS + ((size_t)b * AA + a) * HH + f] = acc;
}

// ---------------------------------------------------------------------------
extern "C" void kernel_launch(void* const* d_in, const int* in_sizes, int n_in,
                              void* d_out, int out_size) {
    const float* doc = (const float*)d_in[0];   // (B,S,H)
    const float* E   = (const float*)d_in[1];   // (A, WIN*H)
    const float* P   = (const float*)d_in[2];   // (A,H,H)
    float* out = (float*)d_out;                 // [attn (B,A,S) | rep (B,A,H)]

    size_t sm2 = (size_t)(GROWS * HH + HH * WIN * 8) * sizeof(float);  // ~88.1 KB
    cudaFuncSetAttribute(k_logits, cudaFuncAttributeMaxDynamicSharedMemorySize, (int)sm2);

    k_prep<<<dim3(AA, 4), 128>>>(P, E);
    k_logits<<<dim3(SS / STILE, BB), 128, sm2>>>(doc);
    k_softmax<<<AA * BB, 256>>>(out);
    k_ctx<<<dim3(BB, NCH), 256>>>(doc, out);
    k_rep<<<BB * AA, 128>>>(P, out);
}

// round 11
// speedup vs baseline: 1.1944x; 1.1491x over previous
#include <cuda_runtime.h>
#include <math.h>

// Problem constants
#define BB 64
#define SS 1024
#define HH 128
#define HHF 64               // h per logits block (h-split)
#define AA 8
#define WIN 5
#define PADW 2
#define STILE 128            // s-tile for logits kernel
#define GROWS (STILE + 4)    // 132 padded rows in logits tile
#define CCH 128              // s per ctx block (R7-proven)
#define NCH (SS / CCH)       // 8 coarse ctx chunks
#define RPW 1028             // ctx rbuf pitch (floats)

// Scratch (no allocations allowed)
// Packed G: [h][w][8] with inner order (a0,a4,a1,a5,a2,a6,a3,a7) so a 16B load
// yields two 64-bit (G[a],G[a+4]) pairs for fma.rn.f32x2.
__device__ float4 gGp4[HH * WIN * 2];                // 128*5*8 floats
__device__ float gLogits[2 * AA * BB * SS];          // [hb][a][b][s] partials
__device__ float gCtxPart[NCH * AA * BB * HH];       // [sc][a][b][h]  (2.1MB)

__device__ __forceinline__ void fma2(unsigned long long& acc,
                                     unsigned long long d2,
                                     unsigned long long g2) {
    asm("fma.rn.f32x2 %0, %1, %2, %3;" : "=l"(acc) : "l"(d2), "l"(g2), "l"(acc));
}
__device__ __forceinline__ unsigned long long dup2(float v) {
    unsigned long long r;
    asm("mov.b64 %0, {%1, %1};" : "=l"(r) : "f"(v));
    return r;
}
__device__ __forceinline__ unsigned long long pk2(float lo, float hi) {
    unsigned long long r;
    asm("mov.b64 %0, {%1, %2};" : "=l"(r) : "f"(lo), "f"(hi));
    return r;
}
__device__ __forceinline__ void unpk(unsigned long long p, float& lo, float& hi) {
    asm("mov.b64 {%0, %1}, %2;" : "=f"(lo), "=f"(hi) : "l"(p));
}

// ---------------------------------------------------------------------------
// K1: G[a,h,w] = sum_f P[a,h,f] * E[a,f,w]; packed scatter to gGp4.
// grid = (A, 4), block = 128. thread: h = hg*32 + (t>>2), f-quarter q = t&3.
// ---------------------------------------------------------------------------
__global__ void k_prep(const float* __restrict__ P, const float* __restrict__ E) {
    __shared__ float Esm[HH * WIN];
    int a = blockIdx.x, hg = blockIdx.y, t = threadIdx.x;
    int h = hg * 32 + (t >> 2), q = t & 3;

    for (int i = t; i < HH * WIN; i += 128)
        Esm[i] = E[(size_t)a * HH * WIN + i];
    __syncthreads();

    const float4* Pp = (const float4*)(P + (size_t)a * HH * HH + h * HH + q * 32);
    float g[WIN] = {0.f, 0.f, 0.f, 0.f, 0.f};
    #pragma unroll
    for (int i = 0; i < 8; ++i) {
        float4 p = Pp[i];
        int f0 = q * 32 + i * 4;
        #pragma unroll
        for (int w = 0; w < WIN; ++w) {
            g[w] += p.x * Esm[(f0 + 0) * WIN + w];
            g[w] += p.y * Esm[(f0 + 1) * WIN + w];
            g[w] += p.z * Esm[(f0 + 2) * WIN + w];
            g[w] += p.w * Esm[(f0 + 3) * WIN + w];
        }
    }
    #pragma unroll
    for (int w = 0; w < WIN; ++w) {
        g[w] += __shfl_xor_sync(0xffffffffu, g[w], 1);
        g[w] += __shfl_xor_sync(0xffffffffu, g[w], 2);
    }
    if (q == 0) {
        float* Gp = (float*)gGp4;
        #pragma unroll
        for (int w = 0; w < WIN; ++w)
            Gp[(h * WIN + w) * 8 + (a & 3) * 2 + (a >> 2)] = g[w];
    }
}

// ---------------------------------------------------------------------------
// K2: logits partial over one h-half.
// gLogits[hb][a][b][s] = sum_w sum_{h in half} doc[b,s+w-2,h] * G[a,h,w]
// R7 inner mix exactly (lane -> 4 consecutive s, 8 taps, 80 FFMA2/h-iter);
// warp -> 16-h split of the 64-h half. dsm [GROWS][64], swizzle
// col = h' ^ ((row>>2)&31). smem 44KB -> 5 blocks/SM (20 warps).
// grid = (S/128, B, 2), block = 128.
// ---------------------------------------------------------------------------
__global__ void __launch_bounds__(128) k_logits(const float* __restrict__ doc) {
    extern __shared__ float sm[];
    float* dsm = sm;                         // [GROWS][64] swizzled
    float* Gsm = sm + GROWS * HHF;           // [64*WIN*8] packed pairs (half)
    int b  = blockIdx.y;
    int s0 = blockIdx.x * STILE;
    int hb = blockIdx.z;
    int t  = threadIdx.x;
    int wid = t >> 5, lane = t & 31;

    {   // Copy this half's packed G (2560 floats = 640 float4)
        const float4* src = gGp4 + (size_t)hb * HHF * WIN * 2;
        float4* dst = (float4*)Gsm;
        #pragma unroll
        for (int i = t; i < HHF * WIN * 2; i += 128) dst[i] = src[i];
    }

    // Tile fill: warp per row, float2 gmem loads of this h-half (256B
    // coalesced), TWO SCALAR swizzled stores (swz may be odd -> element c
    // must land at index c^swz individually; a float2 store would be
    // misaligned and wrong for odd swz).
    const float* db = doc + ((size_t)b * SS) * HH + hb * HHF;
    for (int row = wid; row < GROWS; row += 4) {
        int gs = s0 - PADW + row;
        int swz = (row >> 2) & 31;
        float2 v = make_float2(0.f, 0.f);
        if (gs >= 0 && gs < SS)
            v = *((const float2*)(db + (size_t)gs * HH) + lane);
        int c = 2 * lane;
        dsm[row * HHF + ((c + 0) ^ swz)] = v.x;
        dsm[row * HHF + ((c + 1) ^ swz)] = v.y;
    }
    __syncthreads();

    int h0 = wid * 16;
    int st0 = 4 * lane;
    unsigned long long acc[4][4];
    #pragma unroll
    for (int i = 0; i < 4; ++i)
        #pragma unroll
        for (int p = 0; p < 4; ++p) acc[i][p] = 0ull;

    #pragma unroll 2
    for (int hh = 0; hh < 16; ++hh) {
        int h = h0 + hh;                       // local h in [0,64)
        unsigned long long d[8];
        #pragma unroll
        for (int r = 0; r < 8; ++r) {
            int row = st0 + r;
            d[r] = dup2(dsm[row * HHF + (h ^ ((row >> 2) & 31))]);
        }
        const float* gh = &Gsm[h * (WIN * 8)];
        #pragma unroll
        for (int w = 0; w < WIN; ++w) {
            ulonglong2 g01 = *(const ulonglong2*)(gh + w * 8);
            ulonglong2 g23 = *(const ulonglong2*)(gh + w * 8 + 4);
            #pragma unroll
            for (int si = 0; si < 4; ++si) {
                fma2(acc[si][0], d[si + w], g01.x);
                fma2(acc[si][1], d[si + w], g01.y);
                fma2(acc[si][2], d[si + w], g23.x);
                fma2(acc[si][3], d[si + w], g23.y);
            }
        }
    }

    __syncthreads();
    float* red = sm;   // 128*33 floats = 16.9KB, fits in dsm region
    #pragma unroll
    for (int si = 0; si < 4; ++si) {
        int st = st0 + si;
        #pragma unroll
        for (int p = 0; p < 4; ++p) {
            float lo, hi;
            unpk(acc[si][p], lo, hi);
            red[st * 33 + p * 4 + wid] = lo;           // aspect p
            red[st * 33 + (p + 4) * 4 + wid] = hi;     // aspect p+4
        }
    }
    __syncthreads();

    int st = t;
    #pragma unroll
    for (int a = 0; a < AA; ++a) {
        const float* rp = &red[st * 33 + a * 4];
        float v = rp[0] + rp[1] + rp[2] + rp[3];
        gLogits[(((size_t)hb * AA + a) * BB + b) * SS + s0 + st] = v;
    }
}

// ---------------------------------------------------------------------------
// K3: attn = softmax_s(half0 + half1); write to out[b][a][s]
// grid = A*B (row = a*B + b), block = 256
// ---------------------------------------------------------------------------
__global__ void k_softmax(float* __restrict__ out) {
    int row = blockIdx.x;
    int a = row >> 6;
    int b = row & 63;
    const float* lg0 = gLogits + (size_t)row * SS;
    const float* lg1 = lg0 + (size_t)AA * BB * SS;
    int t = threadIdx.x;

    float v[4];
    float m = -3.4e38f;
    #pragma unroll
    for (int i = 0; i < 4; ++i) {
        v[i] = lg0[t + i * 256] + lg1[t + i * 256];
        m = fmaxf(m, v[i]);
    }

    __shared__ float redm[8];
    #pragma unroll
    for (int o = 16; o > 0; o >>= 1) m = fmaxf(m, __shfl_xor_sync(0xffffffffu, m, o));
    if ((t & 31) == 0) redm[t >> 5] = m;
    __syncthreads();
    m = redm[0];
    #pragma unroll
    for (int i = 1; i < 8; ++i) m = fmaxf(m, redm[i]);

    float sl = 0.f;
    #pragma unroll
    for (int i = 0; i < 4; ++i) { v[i] = __expf(v[i] - m); sl += v[i]; }
    __shared__ float reds[8];
    #pragma unroll
    for (int o = 16; o > 0; o >>= 1) sl += __shfl_xor_sync(0xffffffffu, sl, o);
    if ((t & 31) == 0) reds[t >> 5] = sl;
    __syncthreads();
    float tot = 0.f;
    #pragma unroll
    for (int i = 0; i < 8; ++i) tot += reds[i];
    float inv = 1.0f / tot;

    float* op = out + ((size_t)b * AA + a) * SS;
    #pragma unroll
    for (int i = 0; i < 4; ++i) op[t + i * 256] = v[i] * inv;
}

// ---------------------------------------------------------------------------
// K4: ctx partials (R7-proven version, verbatim). grid = (B, 8), block = 128.
// Warp w owns s in [w*32, w*32+32); lane = h-quad (LDG.128, 512B/warp-inst).
// 4-warp smem reduce (pitch RPW), coalesced store.
// ---------------------------------------------------------------------------
__global__ void __launch_bounds__(128) k_ctx(const float* __restrict__ doc,
                                             const float* __restrict__ attn) {
    int b = blockIdx.x, sc = blockIdx.y;
    int t = threadIdx.x, w = t >> 5, lane = t & 31;

    __shared__ float asmem[AA * CCH];     // 4KB
    __shared__ float rbuf[4 * RPW];       // 16.4KB
    #pragma unroll
    for (int i = t; i < AA * CCH; i += 128) {
        int a = i >> 7, s = i & 127;
        asmem[i] = attn[((size_t)b * AA + a) * SS + sc * CCH + s];
    }
    __syncthreads();

    const float4* dp = (const float4*)(doc + ((size_t)b * SS + sc * CCH) * HH) + lane;
    unsigned long long acc[AA][2];
    #pragma unroll
    for (int a = 0; a < AA; ++a) { acc[a][0] = 0ull; acc[a][1] = 0ull; }

    int sb = w * 32;
    #pragma unroll 8
    for (int i = 0; i < 32; ++i) {
        int s = sb + i;
        float4 dv = dp[s * 32];                    // coalesced 512B/warp LDG.128
        unsigned long long dxy = pk2(dv.x, dv.y);
        unsigned long long dzw = pk2(dv.z, dv.w);
        #pragma unroll
        for (int a = 0; a < AA; ++a) {
            unsigned long long av = dup2(asmem[a * CCH + s]);   // broadcast
            fma2(acc[a][0], dxy, av);
            fma2(acc[a][1], dzw, av);
        }
    }

    #pragma unroll
    for (int a = 0; a < AA; ++a) {
        float4 o;
        unpk(acc[a][0], o.x, o.y);
        unpk(acc[a][1], o.z, o.w);
        *(float4*)&rbuf[w * RPW + a * HH + lane * 4] = o;   // conflict-free STS.128
    }
    __syncthreads();

    // Reduce over the 4 warps: thread t -> h = t; k -> aspect.
    #pragma unroll
    for (int k = 0; k < AA; ++k) {
        int slot = k * HH + t;
        float v = (rbuf[slot] + rbuf[RPW + slot]) +
                  (rbuf[2 * RPW + slot] + rbuf[3 * RPW + slot]);
        gCtxPart[(((size_t)sc * AA + k) * BB + b) * HH + t] = v;   // coalesced
    }
}

// ---------------------------------------------------------------------------
// K5: rep[b,a,f] = sum_h ctx[a,b,h] * P[a,h,f], ctx reduced over 8 partials
// grid = B*A (blk = b*A + a), block = 128 (thread = f)
// ---------------------------------------------------------------------------
__global__ void k_rep(const float* __restrict__ P, float* __restrict__ out) {
    int blk = blockIdx.x;
    int a = blk & 7, b = blk >> 3;
    int f = threadIdx.x;
    __shared__ float csm[HH];
    float c = 0.f;
    #pragma unroll
    for (int sc = 0; sc < NCH; ++sc)
        c += gCtxPart[(((size_t)sc * AA + a) * BB + b) * HH + f];
    csm[f] = c;
    __syncthreads();

    float acc = 0.f;
    const float* Pp = P + (size_t)a * HH * HH + f;
    #pragma unroll 8
    for (int h = 0; h < HH; ++h) acc += csm[h] * Pp[(size_t)h * HH];

    out[(size_t)BB * AA * SS + ((size_t)b * AA + a) * HH + f] = acc;
}

// ---------------------------------------------------------------------------
extern "C" void kernel_launch(void* const* d_in, const int* in_sizes, int n_in,
                              void* d_out, int out_size) {
    const float* doc = (const float*)d_in[0];   // (B,S,H)
    const float* E   = (const float*)d_in[1];   // (A, WIN*H)
    const float* P   = (const float*)d_in[2];   // (A,H,H)
    float* out = (float*)d_out;                 // [attn (B,A,S) | rep (B,A,H)]

    size_t sm2 = (size_t)(GROWS * HHF + HHF * WIN * 8) * sizeof(float);  // ~44 KB
    cudaFuncSetAttribute(k_logits, cudaFuncAttributeMaxDynamicSharedMemorySize, (int)sm2);

    k_prep<<<dim3(AA, 4), 128>>>(P, E);
    k_logits<<<dim3(SS / STILE, BB, 2), 128, sm2>>>(doc);
    k_softmax<<<AA * BB, 256>>>(out);
    k_ctx<<<dim3(BB, NCH), 128>>>(doc, out);
    k_rep<<<BB * AA, 128>>>(P, out);
}